// round 7
// baseline (speedup 1.0000x reference)
#include <cuda_runtime.h>
#include <math.h>
#include <stdint.h>

#define N_TOK 32768
#define DIM   768
#define HID   3072
#define NEXP  8
#define CAP   10240
#define MTILES (CAP / 128)          // 80 (A/H blob granularity stays 128 rows)
#define KCH1  (DIM / 32)            // 24
#define KCH2  (HID / 32)            // 96

// ---------------------------------------------------------------------------
// Scratch (device globals)
// Fragment-blob layout: a 16KB blob = [sub][t(32)][j(4)] float units
//   A-blob (128m x 32k):  unit q = (m16blk*4 + ks)*32 + t
//   B-blob (32k x 128n):  unit q = (ks*8 + p)*32 + t
// ---------------------------------------------------------------------------
__device__ int   g_cnt[NEXP];
__device__ int   g_route_e[N_TOK * 2];
__device__ float g_route_w[N_TOK * 2];
__device__ int   g_tokidx[NEXP * CAP];
__device__ int   g_slot[N_TOK * 2];
__device__ float g_xg [(size_t)NEXP * MTILES * KCH1 * 4096];
__device__ float g_w1f[(size_t)NEXP * (HID/128) * KCH1 * 4096];
__device__ float g_w2f[(size_t)NEXP * (DIM/128) * KCH2 * 4096];
__device__ float g_H  [(size_t)NEXP * MTILES * KCH2 * 4096];
__device__ float g_Y  [(size_t)NEXP * CAP * DIM];

// ---------------------------------------------------------------------------
// Helpers
// ---------------------------------------------------------------------------
__device__ __forceinline__ float tf32r(float x) {
    uint32_t u;
    asm("cvt.rna.tf32.f32 %0, %1;" : "=r"(u) : "f"(x));
    return __uint_as_float(u);
}
__device__ __forceinline__ void cp16(void* dst, const float* src) {
    uint32_t d;
    asm("{ .reg .u64 t; cvta.to.shared.u64 t, %1; cvt.u32.u64 %0, t; }" : "=r"(d) : "l"(dst));
    asm volatile("cp.async.cg.shared.global [%0], [%1], 16;" :: "r"(d), "l"(src));
}
#define CP_COMMIT() asm volatile("cp.async.commit_group;" ::: "memory")
#define CP_WAIT1()  asm volatile("cp.async.wait_group 1;" ::: "memory")

#define MMA_TF32(c, a, b) \
    asm volatile("mma.sync.aligned.m16n8k8.row.col.f32.tf32.tf32.f32 " \
        "{%0,%1,%2,%3}, {%4,%5,%6,%7}, {%8,%9}, {%0,%1,%2,%3};" \
        : "+f"((c)[0]), "+f"((c)[1]), "+f"((c)[2]), "+f"((c)[3]) \
        : "r"((a)[0]), "r"((a)[1]), "r"((a)[2]), "r"((a)[3]), \
          "r"((b)[0]), "r"((b)[1]))

// ---------------------------------------------------------------------------
// Kernel 0: zero counters
// ---------------------------------------------------------------------------
__global__ void zero_counts_kernel() {
    if (threadIdx.x < NEXP) g_cnt[threadIdx.x] = 0;
}

// ---------------------------------------------------------------------------
// Kernel 1: router (one warp per token, exact fp32)
// ---------------------------------------------------------------------------
__global__ __launch_bounds__(256) void router_kernel(
    const float* __restrict__ x, const float* __restrict__ wg)
{
    int warp = (blockIdx.x * blockDim.x + threadIdx.x) >> 5;
    int lane = threadIdx.x & 31;
    if (warp >= N_TOK) return;
    const float* xr = x + (size_t)warp * DIM;

    float acc[NEXP];
#pragma unroll
    for (int e = 0; e < NEXP; e++) acc[e] = 0.f;
    for (int j = lane; j < DIM; j += 32) {
        float xv = xr[j];
        const float* wr = wg + j * NEXP;
#pragma unroll
        for (int e = 0; e < NEXP; e++) acc[e] += xv * wr[e];
    }
#pragma unroll
    for (int e = 0; e < NEXP; e++) {
#pragma unroll
        for (int o = 16; o > 0; o >>= 1)
            acc[e] += __shfl_xor_sync(0xffffffffu, acc[e], o);
    }
    if (lane == 0) {
        int e0 = 0; float v0 = acc[0];
#pragma unroll
        for (int e = 1; e < NEXP; e++) if (acc[e] > v0) { v0 = acc[e]; e0 = e; }
        int e1 = -1; float v1 = -3.4e38f;
#pragma unroll
        for (int e = 0; e < NEXP; e++) if (e != e0 && acc[e] > v1) { v1 = acc[e]; e1 = e; }
        float ex = expf(v1 - v0);
        float s  = 1.f + ex;
        g_route_e[2 * warp + 0] = e0;  g_route_w[2 * warp + 0] = 1.f / s;
        g_route_e[2 * warp + 1] = e1;  g_route_w[2 * warp + 1] = ex / s;
    }
}

// ---------------------------------------------------------------------------
// Kernel 2: slot assignment
// ---------------------------------------------------------------------------
__global__ void assign_kernel() {
    int t = blockIdx.x * blockDim.x + threadIdx.x;
    if (t >= N_TOK) return;
#pragma unroll
    for (int k = 0; k < 2; k++) {
        int e = g_route_e[2 * t + k];
        int pos = atomicAdd(&g_cnt[e], 1);
        if (pos < CAP) {
            g_tokidx[e * CAP + pos] = t;
            g_slot[2 * t + k] = e * CAP + pos;
        } else {
            g_slot[2 * t + k] = -1;
        }
    }
}

// ---------------------------------------------------------------------------
// Kernel 3: weight -> B-blob transform + tf32 round
// ---------------------------------------------------------------------------
__global__ __launch_bounds__(128) void wtransform_kernel(
    const float* __restrict__ w, float* __restrict__ out, int KD, int ND)
{
    const int nkc = KD / 32;
    const int e  = blockIdx.y;
    const int nt = blockIdx.x / nkc;
    const int kc = blockIdx.x % nkc;
    __shared__ float tile[32][132];

    const int tid = threadIdx.x;
    const float* src = w + ((size_t)e * KD + kc * 32) * ND + nt * 128;
#pragma unroll
    for (int u = tid; u < 1024; u += 128) {
        int r = u >> 5, c = (u & 31) * 4;
        float4 v = *(const float4*)(src + (size_t)r * ND + c);
        tile[r][c + 0] = tf32r(v.x);
        tile[r][c + 1] = tf32r(v.y);
        tile[r][c + 2] = tf32r(v.z);
        tile[r][c + 3] = tf32r(v.w);
    }
    __syncthreads();

    float4* dst = (float4*)(out + ((size_t)(e * (ND / 128) + nt) * nkc + kc) * 4096);
#pragma unroll
    for (int u = tid; u < 1024; u += 128) {
        int t = u & 31, p = (u >> 5) & 7, ks = u >> 8;
        int gid = t >> 2, tig = t & 3;
        float4 v;
        v.x = tile[ks * 8 + tig    ][p * 16 + gid];
        v.y = tile[ks * 8 + tig + 4][p * 16 + gid];
        v.z = tile[ks * 8 + tig    ][p * 16 + 8 + gid];
        v.w = tile[ks * 8 + tig + 4][p * 16 + 8 + gid];
        dst[u] = v;
    }
}

// ---------------------------------------------------------------------------
// Kernel 4: gather routed tokens into A-blobs (tf32-rounded)
// ---------------------------------------------------------------------------
__global__ __launch_bounds__(256) void gather_frag_kernel(const float* __restrict__ x) {
    const int e = blockIdx.y;
    const int Me = min(g_cnt[e], CAP);
    const int g16 = blockIdx.x;
    const int base = g16 * 16;
    if (base >= Me) return;

    __shared__ float rows[16][772];
    const int tid = threadIdx.x;

    for (int u = tid; u < 16 * 192; u += 256) {
        int r = u / 192, c = (u % 192) * 4;
        int pos = base + r;
        if (pos < Me) {
            int tok = g_tokidx[e * CAP + pos];
            float4 v = *(const float4*)(x + (size_t)tok * DIM + c);
            rows[r][c + 0] = tf32r(v.x);
            rows[r][c + 1] = tf32r(v.y);
            rows[r][c + 2] = tf32r(v.z);
            rows[r][c + 3] = tf32r(v.w);
        } else {
            rows[r][c + 0] = 0.f; rows[r][c + 1] = 0.f;
            rows[r][c + 2] = 0.f; rows[r][c + 3] = 0.f;
        }
    }
    __syncthreads();

    const int mtile = g16 >> 3, m16blk = g16 & 7;
    float4* outb = (float4*)g_xg;
    for (int u = tid; u < 16 * 192; u += 256) {
        int kc = u >> 7, w = u & 127, t = w & 31;
        int ks = (w >> 5) & 3;
        int gid = t >> 2, tig = t & 3;
        int col = kc * 32 + ks * 8 + tig;
        float4 v;
        v.x = rows[gid    ][col];
        v.y = rows[gid + 8][col];
        v.z = rows[gid    ][col + 4];
        v.w = rows[gid + 8][col + 4];
        outb[((size_t)((e * MTILES + mtile) * KCH1 + kc)) * 1024 + m16blk * 128 + w] = v;
    }
}

// ---------------------------------------------------------------------------
// Fragment-major tf32 GEMM. CTA 256x128, 8 warps (4x2), warp tile 64x64.
//   acc[4][8][4] = 128 regs/thread. 3-stage cp.async pipeline, 48KB/stage.
//   Mainloop per warp-ks: 8 LDS.128 + 32 MMA.
// ---------------------------------------------------------------------------
template<int NKCH, int NDIM, bool EPI_FRAG>
__global__ __launch_bounds__(256, 1) void gemm_frag_kernel(
    const float* __restrict__ Ablobs,
    const float* __restrict__ Bblobs,
    const float* __restrict__ bias,
    float* __restrict__ Cout)
{
    const int e  = blockIdx.z;
    const int Me = min(g_cnt[e], CAP);
    const int m0 = blockIdx.y * 256;
    if (m0 >= Me) return;
    const int bx = blockIdx.x;
    const int mt0 = blockIdx.y * 2;       // first 128-row blob index

    extern __shared__ float smem[];       // 3 stages x 12288 floats (48KB)
    const int tid = threadIdx.x;
    const int wid = tid >> 5, lid = tid & 31;
    const int gid = lid >> 2, tig = lid & 3;
    const int wMblk = (wid >> 1) * 4;     // m16 block base (0,4,8,12)
    const int pbase = (wid & 1) * 4;      // B pair base (0 or 4)

    const float* Ab0 = Ablobs + ((size_t)(e * MTILES + mt0    ) * NKCH) * 4096;
    const float* Ab1 = Ablobs + ((size_t)(e * MTILES + mt0 + 1) * NKCH) * 4096;
    const float* Bb  = Bblobs + ((size_t)(e * (NDIM / 128) + bx) * NKCH) * 4096;

    float acc[4][8][4];
#pragma unroll
    for (int mf = 0; mf < 4; mf++)
#pragma unroll
        for (int nf = 0; nf < 8; nf++)
#pragma unroll
            for (int q = 0; q < 4; q++) acc[mf][nf][q] = 0.f;

    auto issue = [&](int i) {
        float* dst = smem + (i % 3) * 12288;
        const float* a0 = Ab0 + (size_t)i * 4096;
        const float* a1 = Ab1 + (size_t)i * 4096;
        const float* b  = Bb  + (size_t)i * 4096;
#pragma unroll
        for (int j = 0; j < 4; j++)
            cp16(dst + (j * 256 + tid) * 4, a0 + (j * 256 + tid) * 4);
#pragma unroll
        for (int j = 0; j < 4; j++)
            cp16(dst + 4096 + (j * 256 + tid) * 4, a1 + (j * 256 + tid) * 4);
#pragma unroll
        for (int j = 0; j < 4; j++)
            cp16(dst + 8192 + (j * 256 + tid) * 4, b + (j * 256 + tid) * 4);
        CP_COMMIT();
    };

    issue(0);
    issue(1);

    for (int i = 0; i < NKCH; i++) {
        CP_WAIT1();
        __syncthreads();
        if (i + 2 < NKCH) issue(i + 2); else CP_COMMIT();

        const float4* pA = (const float4*)(smem + (i % 3) * 12288);  // 2048 f4 (2 blobs)
        const float4* pB = pA + 2048;
#pragma unroll
        for (int ks = 0; ks < 4; ks++) {
            uint32_t a[4][4], b[8][2];
#pragma unroll
            for (int mf = 0; mf < 4; mf++) {
                float4 v = pA[((wMblk + mf) * 4 + ks) * 32 + lid];
                a[mf][0] = __float_as_uint(v.x);
                a[mf][1] = __float_as_uint(v.y);
                a[mf][2] = __float_as_uint(v.z);
                a[mf][3] = __float_as_uint(v.w);
            }
#pragma unroll
            for (int q = 0; q < 4; q++) {
                float4 v = pB[(ks * 8 + pbase + q) * 32 + lid];
                b[2 * q + 0][0] = __float_as_uint(v.x);
                b[2 * q + 0][1] = __float_as_uint(v.y);
                b[2 * q + 1][0] = __float_as_uint(v.z);
                b[2 * q + 1][1] = __float_as_uint(v.w);
            }
#pragma unroll
            for (int mf = 0; mf < 4; mf++)
#pragma unroll
                for (int nf = 0; nf < 8; nf++)
                    MMA_TF32(acc[mf][nf], a[mf], b[nf]);
        }
    }

    const int warpM = (wid >> 1) * 64;    // 0,64,128,192
    const int warpN = (wid & 1) * 64;
    const int n0 = bx * 128;
    const float* bp = bias + (size_t)e * NDIM + n0 + warpN;

    if (EPI_FRAG) {
        // emit H blobs for mtiles mt0 (+h), kcs bx*4 .. bx*4+3; two 64KB halves
#pragma unroll
        for (int h = 0; h < 2; h++) {
            __syncthreads();
            if ((wid >> 2) == h) {
#pragma unroll
                for (int mf = 0; mf < 4; mf++)
#pragma unroll
                    for (int half = 0; half < 2; half++) {
                        int ml = warpM - h * 128 + mf * 16 + gid + half * 8; // 0..127
                        int mm = ml & 15, m16blk = ml >> 4;
#pragma unroll
                        for (int nf = 0; nf < 8; nf++)
#pragma unroll
                            for (int c = 0; c < 2; c++) {
                                int n_local = warpN + nf * 8 + tig * 2 + c;
                                float v = acc[mf][nf][half * 2 + c] + bp[nf * 8 + tig * 2 + c];
                                v = tf32r(0.5f * v * (1.f + erff(v * 0.70710678118654752f)));
                                int kc = n_local >> 5, ks = (n_local >> 3) & 3;
                                int t = (mm & 7) * 4 + (n_local & 3);
                                int j = ((n_local >> 2) & 1) * 2 + (mm >> 3);
                                int tw = t ^ (((t >> 3) & 3) << 1);
                                smem[(kc * 1024 + (m16blk * 4 + ks) * 32 + tw) * 4 + j] = v;
                            }
                    }
            }
            __syncthreads();
            float4* dst = (float4*)(Cout +
                ((size_t)((e * MTILES + mt0 + h) * KCH2 + bx * 4)) * 4096);
            const float4* st = (const float4*)smem;
#pragma unroll
            for (int u = tid; u < 4096; u += 256) {
                int t = u & 31;
                int tw = t ^ (((t >> 3) & 3) << 1);
                dst[u] = st[(u & ~31) | tw];
            }
        }
    } else {
#pragma unroll
        for (int mf = 0; mf < 4; mf++)
#pragma unroll
            for (int half = 0; half < 2; half++) {
                int m = m0 + warpM + mf * 16 + gid + half * 8;
                if (m >= Me) continue;
                float* Crow = Cout + (size_t)(e * CAP + m) * NDIM + n0 + warpN;
#pragma unroll
                for (int nf = 0; nf < 8; nf++) {
                    float2 o;
                    o.x = acc[mf][nf][half * 2 + 0] + bp[nf * 8 + tig * 2 + 0];
                    o.y = acc[mf][nf][half * 2 + 1] + bp[nf * 8 + tig * 2 + 1];
                    *(float2*)(Crow + nf * 8 + tig * 2) = o;
                }
            }
    }
}

// ---------------------------------------------------------------------------
// combine + LayerNorm
// ---------------------------------------------------------------------------
__global__ __launch_bounds__(256) void combine_ln_kernel(
    const float* __restrict__ lnw,
    const float* __restrict__ lnb,
    float* __restrict__ out)
{
    const int t   = blockIdx.x;
    const int tid = threadIdx.x;
    const int s0  = g_slot[2 * t + 0];
    const int s1  = g_slot[2 * t + 1];
    const float w0 = g_route_w[2 * t + 0];
    const float w1 = g_route_w[2 * t + 1];

    float v[3];
    float sum = 0.f;
#pragma unroll
    for (int r = 0; r < 3; r++) {
        int i = r * 256 + tid;
        float a = (s0 >= 0) ? g_Y[(size_t)s0 * DIM + i] : 0.f;
        float b = (s1 >= 0) ? g_Y[(size_t)s1 * DIM + i] : 0.f;
        v[r] = w0 * a + w1 * b;
        sum += v[r];
    }

    __shared__ float red[256];
    red[tid] = sum;
    __syncthreads();
#pragma unroll
    for (int o = 128; o > 0; o >>= 1) {
        if (tid < o) red[tid] += red[tid + o];
        __syncthreads();
    }
    float mu = red[0] * (1.f / (float)DIM);
    __syncthreads();

    float sq = 0.f;
#pragma unroll
    for (int r = 0; r < 3; r++) { float d = v[r] - mu; sq += d * d; }
    red[tid] = sq;
    __syncthreads();
#pragma unroll
    for (int o = 128; o > 0; o >>= 1) {
        if (tid < o) red[tid] += red[tid + o];
        __syncthreads();
    }
    float rstd = rsqrtf(red[0] * (1.f / (float)DIM) + 1e-5f);

#pragma unroll
    for (int r = 0; r < 3; r++) {
        int i = r * 256 + tid;
        out[(size_t)t * DIM + i] = (v[r] - mu) * rstd * lnw[i] + lnb[i];
    }
}

// ---------------------------------------------------------------------------
// Launch
// ---------------------------------------------------------------------------
extern "C" void kernel_launch(void* const* d_in, const int* in_sizes, int n_in,
                              void* d_out, int out_size)
{
    const float* x   = (const float*)d_in[0];
    const float* wg  = (const float*)d_in[1];
    const float* w1  = (const float*)d_in[2];
    const float* b1  = (const float*)d_in[3];
    const float* w2  = (const float*)d_in[4];
    const float* b2  = (const float*)d_in[5];
    const float* lnw = (const float*)d_in[6];
    const float* lnb = (const float*)d_in[7];
    float* out = (float*)d_out;

    const int SMEM_BYTES = 3 * 12288 * 4;   // 147456
    cudaFuncSetAttribute(gemm_frag_kernel<KCH1, HID, true>,
                         cudaFuncAttributeMaxDynamicSharedMemorySize, SMEM_BYTES);
    cudaFuncSetAttribute(gemm_frag_kernel<KCH2, DIM, false>,
                         cudaFuncAttributeMaxDynamicSharedMemorySize, SMEM_BYTES);

    float* w1f; cudaGetSymbolAddress((void**)&w1f, g_w1f);
    float* w2f; cudaGetSymbolAddress((void**)&w2f, g_w2f);
    float* xg;  cudaGetSymbolAddress((void**)&xg,  g_xg);
    float* Hbuf; cudaGetSymbolAddress((void**)&Hbuf, g_H);
    float* Ybuf; cudaGetSymbolAddress((void**)&Ybuf, g_Y);

    zero_counts_kernel<<<1, 32>>>();
    router_kernel<<<N_TOK / 8, 256>>>(x, wg);
    assign_kernel<<<N_TOK / 256, 256>>>();

    wtransform_kernel<<<dim3((HID / 128) * KCH1, NEXP), 128>>>(w1, w1f, DIM, HID);
    wtransform_kernel<<<dim3((DIM / 128) * KCH2, NEXP), 128>>>(w2, w2f, HID, DIM);

    gather_frag_kernel<<<dim3(CAP / 16, NEXP), 256>>>(x);

    gemm_frag_kernel<KCH1, HID, true><<<dim3(HID / 128, CAP / 256, NEXP), 256, SMEM_BYTES>>>(
        xg, w1f, b1, Hbuf);
    gemm_frag_kernel<KCH2, DIM, false><<<dim3(DIM / 128, CAP / 256, NEXP), 256, SMEM_BYTES>>>(
        Hbuf, w2f, b2, Ybuf);

    combine_ln_kernel<<<N_TOK, 256>>>(lnw, lnb, out);
}